// round 7
// baseline (speedup 1.0000x reference)
#include <cuda_runtime.h>
#include <cuda_fp16.h>
#include <math.h>
#include <stdint.h>

#define BSZ   2
#define SEQ   2048
#define EMB   4096
#define NH    32
#define NKVH  8
#define HD    128
#define GROUPS (NH / NKVH)
#define MROWS (BSZ * SEQ)          // 4096
#define QDIM  (NH * HD)            // 4096
#define KVDIM (NKVH * HD)          // 1024

// log2(e)/sqrt(128), folded into Q so softmax uses bare exp2
#define QSCALE 0.12751744f

// Scratch (device globals)
__device__ __half g_Qa [(size_t)MROWS * EMB];    // half activations
__device__ __half g_Ka [(size_t)MROWS * EMB];
__device__ __half g_Va [(size_t)MROWS * EMB];
__device__ __half g_Qh [(size_t)MROWS * QDIM];   // post-rope half
__device__ __half g_Kh [(size_t)MROWS * KVDIM];
__device__ __half g_Vh [(size_t)MROWS * KVDIM];
__device__ __half g_AOh[(size_t)MROWS * QDIM];
__device__ __half g_Wqh[(size_t)EMB * QDIM];     // [K][N] half (no transpose)
__device__ __half g_Wkh[(size_t)EMB * KVDIM];
__device__ __half g_Wvh[(size_t)EMB * KVDIM];
__device__ __half g_Woh[(size_t)QDIM * EMB];

// ---------------------------------------------------------------------------
// Helpers
// ---------------------------------------------------------------------------
__device__ __forceinline__ uint32_t smem_u32(const void* p) {
    uint32_t a;
    asm("{ .reg .u64 t; cvta.to.shared.u64 t, %1; cvt.u32.u64 %0, t; }" : "=r"(a) : "l"(p));
    return a;
}
__device__ __forceinline__ void cpasync16(uint32_t dst, const void* src) {
    asm volatile("cp.async.cg.shared.global [%0], [%1], 16;" :: "r"(dst), "l"(src) : "memory");
}
#define CP_COMMIT() asm volatile("cp.async.commit_group;" ::: "memory")
#define CP_WAIT(n)  asm volatile("cp.async.wait_group %0;" :: "n"(n) : "memory")

__device__ __forceinline__ void mma_f16(float* d, const uint32_t* a, uint32_t b0, uint32_t b1) {
    asm volatile("mma.sync.aligned.m16n8k16.row.col.f32.f16.f16.f32 "
        "{%0,%1,%2,%3}, {%4,%5,%6,%7}, {%8,%9}, {%0,%1,%2,%3};"
        : "+f"(d[0]), "+f"(d[1]), "+f"(d[2]), "+f"(d[3])
        : "r"(a[0]), "r"(a[1]), "r"(a[2]), "r"(a[3]), "r"(b0), "r"(b1));
}
__device__ __forceinline__ void ldsm4(uint32_t& r0, uint32_t& r1, uint32_t& r2, uint32_t& r3,
                                      uint32_t addr) {
    asm volatile("ldmatrix.sync.aligned.m8n8.x4.shared.b16 {%0,%1,%2,%3}, [%4];"
        : "=r"(r0), "=r"(r1), "=r"(r2), "=r"(r3) : "r"(addr));
}
__device__ __forceinline__ void ldsm4t(uint32_t& r0, uint32_t& r1, uint32_t& r2, uint32_t& r3,
                                       uint32_t addr) {
    asm volatile("ldmatrix.sync.aligned.m8n8.x4.trans.shared.b16 {%0,%1,%2,%3}, [%4];"
        : "=r"(r0), "=r"(r1), "=r"(r2), "=r"(r3) : "r"(addr));
}

// ---------------------------------------------------------------------------
// One-shot fp32->half conversion of all 7 tensors. 1024 elems per block.
// ---------------------------------------------------------------------------
struct ConvDesc {
    const float* src[7];
    __half*      dst[7];
    int          nblk[7];
};

__global__ void conv_all(ConvDesc cd)
{
    int b = blockIdx.x;
    int seg = 0;
#pragma unroll
    for (int i = 0; i < 7; i++) {
        if (b >= cd.nblk[i]) { b -= cd.nblk[i]; seg = i + 1; }
        else break;
    }
    const float* src = cd.src[seg];
    __half* dst = cd.dst[seg];
    size_t i = ((size_t)b * 256 + threadIdx.x) * 4;
    float4 v = *(const float4*)(src + i);
    *(__half2*)(dst + i)     = __floats2half2_rn(v.x, v.y);
    *(__half2*)(dst + i + 2) = __floats2half2_rn(v.z, v.w);
}

// ---------------------------------------------------------------------------
// fp16 tensor-core GEMM: C[M,N] = A[M,K] @ B[K,N]  (B row-major, ldsm trans)
// CTA tile 128(M)x256(N), BK=64, 8 warps (warp tile 64x64), cp.async 3-stage,
// single barrier per k-iter. MODE: 0=f32 out, 1=half out, 2=rope+scale half out.
// ---------------------------------------------------------------------------
#define HP 72                     // A row pitch (halves)
#define BP 264                    // B row pitch (halves)
#define SP 264                    // fp32 staging pitch (floats), MODE 2
#define A_ST (128 * HP)
#define B_ST (64 * BP)
#define STG_B ((A_ST + B_ST) * 2)            // 52224 bytes
#define GN_SMEM (3 * STG_B)                  // 156672 bytes

template <int MODE>
__global__ __launch_bounds__(256, 1) void gemm_f16n(const __half* __restrict__ A,
                                                    const __half* __restrict__ B,
                                                    void* __restrict__ Cv,
                                                    int M, int N, int K, float rsc)
{
    extern __shared__ __half smh[];
    const uint32_t sb = smem_u32(smh);

    const int tid  = threadIdx.x;
    const int wid  = tid >> 5, lane = tid & 31;
    const int g    = lane >> 2, tig = lane & 3;
    const int wm   = (wid & 1) * 64;
    const int wn   = (wid >> 1) * 64;
    const int bm   = blockIdx.y * 128, bn = blockIdx.x * 256;

    auto load_tile = [&](int c, int s) {
        const __half* Ab = A + (size_t)bm * K + c * 64;
        const __half* Bb = B + (size_t)(c * 64) * N + bn;
        uint32_t sa  = sb + (uint32_t)s * STG_B;
        uint32_t sbb = sa + A_ST * 2;
#pragma unroll
        for (int l = 0; l < 4; l++) {
            int id = l * 256 + tid;
            int r = id >> 3, c8 = (id & 7) * 8;
            cpasync16(sa + (uint32_t)(r * HP + c8) * 2, Ab + (size_t)r * K + c8);
        }
#pragma unroll
        for (int l = 0; l < 8; l++) {
            int id = l * 256 + tid;
            int r = id >> 5, c8 = (id & 31) * 8;
            cpasync16(sbb + (uint32_t)(r * BP + c8) * 2, Bb + (size_t)r * N + c8);
        }
        CP_COMMIT();
    };

    const int l7  = lane & 7;
    const int lb3 = (lane >> 3) & 1;
    const int lb4 = lane >> 4;

    float acc[4][8][4];
#pragma unroll
    for (int mi = 0; mi < 4; mi++)
#pragma unroll
        for (int ni = 0; ni < 8; ni++)
#pragma unroll
            for (int r = 0; r < 4; r++) acc[mi][ni][r] = 0.0f;

    const int iters = K / 64;
    load_tile(0, 0);
    load_tile(1, 1);

    for (int c = 0; c < iters; c++) {
        const int s = c % 3;
        if (c + 1 < iters) { CP_WAIT(1); } else { CP_WAIT(0); }
        __syncthreads();
        if (c + 2 < iters) load_tile(c + 2, (c + 2) % 3);

        const uint32_t sA  = sb + (uint32_t)s * STG_B;
        const uint32_t sBb = sA + A_ST * 2;

#pragma unroll
        for (int ks = 0; ks < 4; ks++) {
            const int kb = ks * 16;
            uint32_t af[4][4], bf[4][4];
#pragma unroll
            for (int mi = 0; mi < 4; mi++) {
                uint32_t addr = sA + (uint32_t)((wm + mi * 16 + l7 + lb3 * 8) * HP
                                                + kb + lb4 * 8) * 2;
                ldsm4(af[mi][0], af[mi][1], af[mi][2], af[mi][3], addr);
            }
#pragma unroll
            for (int nj = 0; nj < 4; nj++) {
                uint32_t addr = sBb + (uint32_t)((kb + l7 + lb3 * 8) * BP
                                                 + wn + nj * 16 + lb4 * 8) * 2;
                ldsm4t(bf[nj][0], bf[nj][1], bf[nj][2], bf[nj][3], addr);
            }
#pragma unroll
            for (int mi = 0; mi < 4; mi++)
#pragma unroll
                for (int nj = 0; nj < 4; nj++) {
                    mma_f16(acc[mi][nj * 2],     af[mi], bf[nj][0], bf[nj][1]);
                    mma_f16(acc[mi][nj * 2 + 1], af[mi], bf[nj][2], bf[nj][3]);
                }
        }
    }

    if (MODE == 2) {
        // stage fp32 tile in smem, apply RoPE (+scale), write half
        __syncthreads();
        float* S = (float*)smh;
#pragma unroll
        for (int mi = 0; mi < 4; mi++) {
            int r0 = wm + mi * 16 + g;
#pragma unroll
            for (int ni = 0; ni < 8; ni++) {
                int cc = wn + ni * 8 + tig * 2;
                *(float2*)(S + (size_t)r0 * SP + cc)       = make_float2(acc[mi][ni][0], acc[mi][ni][1]);
                *(float2*)(S + (size_t)(r0 + 8) * SP + cc) = make_float2(acc[mi][ni][2], acc[mi][ni][3]);
            }
        }
        __syncthreads();
        __half* C = (__half*)Cv;
        const float LG = 0.2076205059304640f;   // 2*log2(10000)/128
#pragma unroll 4
        for (int l = 0; l < 64; l++) {
            int idx = l * 256 + tid;
            int r  = idx >> 7;
            int pc = idx & 127;
            int h2 = pc >> 6;
            int d  = pc & 63;
            float x1 = S[(size_t)r * SP + h2 * 128 + d];
            float x2 = S[(size_t)r * SP + h2 * 128 + d + 64];
            int grow = bm + r;
            float pos = (float)(grow & (SEQ - 1));
            float invf = exp2f(-LG * (float)d);
            float ang = pos * invf;
            float sn, cs;
            sincosf(ang, &sn, &cs);
            size_t o = (size_t)grow * N + bn + h2 * 128 + d;
            C[o]      = __float2half((x1 * cs - x2 * sn) * rsc);
            C[o + 64] = __float2half((x2 * cs + x1 * sn) * rsc);
        }
    } else {
#pragma unroll
        for (int mi = 0; mi < 4; mi++) {
            int row0 = bm + wm + mi * 16 + g;
#pragma unroll
            for (int ni = 0; ni < 8; ni++) {
                int col = bn + wn + ni * 8 + tig * 2;
                if (MODE == 1) {
                    __half* C = (__half*)Cv;
                    *(__half2*)(C + (size_t)row0 * N + col) =
                        __floats2half2_rn(acc[mi][ni][0], acc[mi][ni][1]);
                    *(__half2*)(C + (size_t)(row0 + 8) * N + col) =
                        __floats2half2_rn(acc[mi][ni][2], acc[mi][ni][3]);
                } else {
                    float* C = (float*)Cv;
                    *(float2*)(C + (size_t)row0 * N + col)       = make_float2(acc[mi][ni][0], acc[mi][ni][1]);
                    *(float2*)(C + (size_t)(row0 + 8) * N + col) = make_float2(acc[mi][ni][2], acc[mi][ni][3]);
                }
            }
        }
    }
}

// ---------------------------------------------------------------------------
// Flash attention v4 (unchanged from R6): fp16 MMA, ldmatrix, 3-stage K/V,
// one barrier per kv-iteration. Q tile 128, K tile 64, 8 warps.
// ---------------------------------------------------------------------------
#define QP 136
#define VP 72
#define KVST (2 * 64 * QP)
#define FL4_SMEM ((128*QP + 3*KVST + 128*VP) * 2)   // 157696 bytes

__global__ __launch_bounds__(256, 1) void flash4(const __half* __restrict__ Q,
                                                 const __half* __restrict__ K,
                                                 const __half* __restrict__ V,
                                                 __half* __restrict__ O)
{
    extern __shared__ __half hs[];
    __half* Qs  = hs;
    __half* KV0 = Qs + 128 * QP;
    __half* Ps  = KV0 + 3 * KVST;

    const uint32_t sbQ  = smem_u32(Qs);
    const uint32_t sbKV = smem_u32(KV0);
    const uint32_t sbP  = smem_u32(Ps);
    __half2* P2 = (__half2*)Ps;

    const int qi  = (int)gridDim.x - 1 - (int)blockIdx.x;
    const int h   = blockIdx.y;
    const int b   = blockIdx.z;
    const int kvh = h / GROUPS;
    const int tid = threadIdx.x;
    const int wid = tid >> 5, lane = tid & 31;
    const int g   = lane >> 2, tig = lane & 3;
    const int wq  = wid * 16;
    const int l7  = lane & 7;
    const int lb3 = (lane >> 3) & 1;
    const int lb4 = lane >> 4;

    const __half* Qg = Q + (size_t)(b * SEQ + qi * 128) * QDIM + h * HD;
    const __half* Kg = K + (size_t)(b * SEQ) * KVDIM + kvh * HD;
    const __half* Vg = V + (size_t)(b * SEQ) * KVDIM + kvh * HD;

    auto load_kv = [&](int kb, int s) {
        const __half* Kt = Kg + (size_t)(kb * 64) * KVDIM;
        const __half* Vt = Vg + (size_t)(kb * 64) * KVDIM;
        uint32_t ks_ = sbKV + (uint32_t)s * (KVST * 2);
        uint32_t vs_ = ks_ + 64 * QP * 2;
#pragma unroll
        for (int l = 0; l < 4; l++) {
            int id = l * 256 + tid;
            int r = id >> 4, c8 = (id & 15) * 8;
            cpasync16(ks_ + (uint32_t)(r * QP + c8) * 2, Kt + (size_t)r * KVDIM + c8);
            cpasync16(vs_ + (uint32_t)(r * QP + c8) * 2, Vt + (size_t)r * KVDIM + c8);
        }
        CP_COMMIT();
    };

#pragma unroll
    for (int l = 0; l < 8; l++) {
        int id = l * 256 + tid;
        int r = id >> 4, c8 = (id & 15) * 8;
        *(uint4*)(Qs + r * QP + c8) = *(const uint4*)(Qg + (size_t)r * QDIM + c8);
    }

    float m0 = -INFINITY, m1 = -INFINITY, l0 = 0.f, l1 = 0.f;
    float oa[16][4];
#pragma unroll
    for (int ni = 0; ni < 16; ni++)
#pragma unroll
        for (int r = 0; r < 4; r++) oa[ni][r] = 0.f;

    const int kmax = 2 * qi + 2;
    load_kv(0, 0);
    load_kv(1, 1);

    for (int kb = 0; kb < kmax; kb++) {
        const int s = kb % 3;
        if (kb + 1 < kmax) { CP_WAIT(1); } else { CP_WAIT(0); }
        __syncthreads();
        if (kb + 2 < kmax) load_kv(kb + 2, (kb + 2) % 3);

        const uint32_t sK = sbKV + (uint32_t)s * (KVST * 2);
        const uint32_t sV = sK + 64 * QP * 2;

        float sa[8][4];
#pragma unroll
        for (int ni = 0; ni < 8; ni++)
#pragma unroll
            for (int r = 0; r < 4; r++) sa[ni][r] = 0.f;

#pragma unroll
        for (int ks = 0; ks < 8; ks++) {
            const int kc = ks * 16;
            uint32_t a[4], bf[8][2];
            {
                uint32_t addr = sbQ + (uint32_t)((wq + l7 + lb3 * 8) * QP + kc + lb4 * 8) * 2;
                ldsm4(a[0], a[1], a[2], a[3], addr);
            }
#pragma unroll
            for (int nip = 0; nip < 4; nip++) {
                uint32_t addr = sK + (uint32_t)((nip * 16 + l7 + lb4 * 8) * QP + kc + lb3 * 8) * 2;
                ldsm4(bf[nip*2][0], bf[nip*2][1], bf[nip*2+1][0], bf[nip*2+1][1], addr);
            }
#pragma unroll
            for (int ni = 0; ni < 8; ni++)
                mma_f16(sa[ni], a, bf[ni][0], bf[ni][1]);
        }

        if (kb >= 2 * qi) {
            int r0 = qi * 128 + wq + g;
#pragma unroll
            for (int ni = 0; ni < 8; ni++) {
                int c0 = kb * 64 + ni * 8 + 2 * tig;
                if (c0 > r0)         sa[ni][0] = -INFINITY;
                if (c0 + 1 > r0)     sa[ni][1] = -INFINITY;
                if (c0 > r0 + 8)     sa[ni][2] = -INFINITY;
                if (c0 + 1 > r0 + 8) sa[ni][3] = -INFINITY;
            }
        }

        float mx0 = -INFINITY, mx1 = -INFINITY;
#pragma unroll
        for (int ni = 0; ni < 8; ni++) {
            mx0 = fmaxf(mx0, fmaxf(sa[ni][0], sa[ni][1]));
            mx1 = fmaxf(mx1, fmaxf(sa[ni][2], sa[ni][3]));
        }
        mx0 = fmaxf(mx0, __shfl_xor_sync(0xffffffffu, mx0, 1));
        mx0 = fmaxf(mx0, __shfl_xor_sync(0xffffffffu, mx0, 2));
        mx1 = fmaxf(mx1, __shfl_xor_sync(0xffffffffu, mx1, 1));
        mx1 = fmaxf(mx1, __shfl_xor_sync(0xffffffffu, mx1, 2));

        float mm0 = fmaxf(m0, mx0), mm1 = fmaxf(m1, mx1);
        float sub0 = (mm0 == -INFINITY) ? 0.f : mm0;
        float sub1 = (mm1 == -INFINITY) ? 0.f : mm1;
        float al0 = exp2f(m0 - sub0);
        float al1 = exp2f(m1 - sub1);
        m0 = mm0; m1 = mm1;

        float ls0 = 0.f, ls1 = 0.f;
#pragma unroll
        for (int ni = 0; ni < 8; ni++) {
            float p0 = exp2f(sa[ni][0] - sub0);
            float p1 = exp2f(sa[ni][1] - sub0);
            float p2 = exp2f(sa[ni][2] - sub1);
            float p3 = exp2f(sa[ni][3] - sub1);
            ls0 += p0 + p1; ls1 += p2 + p3;
            P2[(wq + g) * (VP/2) + ni * 4 + tig]     = __floats2half2_rn(p0, p1);
            P2[(wq + g + 8) * (VP/2) + ni * 4 + tig] = __floats2half2_rn(p2, p3);
        }
        ls0 += __shfl_xor_sync(0xffffffffu, ls0, 1);
        ls0 += __shfl_xor_sync(0xffffffffu, ls0, 2);
        ls1 += __shfl_xor_sync(0xffffffffu, ls1, 1);
        ls1 += __shfl_xor_sync(0xffffffffu, ls1, 2);
        l0 = l0 * al0 + ls0;
        l1 = l1 * al1 + ls1;

#pragma unroll
        for (int ni = 0; ni < 16; ni++) {
            oa[ni][0] *= al0; oa[ni][1] *= al0;
            oa[ni][2] *= al1; oa[ni][3] *= al1;
        }
        __syncwarp();

#pragma unroll
        for (int ks = 0; ks < 4; ks++) {
            const int kc = ks * 16;
            uint32_t a[4];
            {
                uint32_t addr = sbP + (uint32_t)((wq + l7 + lb3 * 8) * VP + kc + lb4 * 8) * 2;
                ldsm4(a[0], a[1], a[2], a[3], addr);
            }
#pragma unroll
            for (int nip = 0; nip < 8; nip++) {
                uint32_t bf0, bf1, bf2, bf3;
                uint32_t addr = sV + (uint32_t)((kc + l7 + lb3 * 8) * QP + nip * 16 + lb4 * 8) * 2;
                ldsm4t(bf0, bf1, bf2, bf3, addr);
                mma_f16(oa[nip*2],     a, bf0, bf1);
                mma_f16(oa[nip*2 + 1], a, bf2, bf3);
            }
        }
    }

    float inv0 = 1.0f / l0, inv1 = 1.0f / l1;
    __half* Og = O + (size_t)(b * SEQ + qi * 128 + wq) * QDIM + h * HD;
#pragma unroll
    for (int ni = 0; ni < 16; ni++) {
        int col = ni * 8 + 2 * tig;
        *(__half2*)(Og + (size_t)g * QDIM + col) =
            __floats2half2_rn(oa[ni][0] * inv0, oa[ni][1] * inv0);
        *(__half2*)(Og + (size_t)(g + 8) * QDIM + col) =
            __floats2half2_rn(oa[ni][2] * inv1, oa[ni][3] * inv1);
    }
}

// ---------------------------------------------------------------------------
// Launch: conv_all -> gemmQ(rope) -> gemmK(rope) -> gemmV(half) -> flash -> gemmO
// ---------------------------------------------------------------------------
extern "C" void kernel_launch(void* const* d_in, const int* in_sizes, int n_in,
                              void* d_out, int out_size)
{
    const float* query = (const float*)d_in[0];
    const float* key   = (const float*)d_in[1];
    const float* value = (const float*)d_in[2];
    const float* Wq = (const float*)d_in[5];
    const float* Wk = (const float*)d_in[6];
    const float* Wv = (const float*)d_in[7];
    const float* Wo = (const float*)d_in[8];
    float* out = (float*)d_out;

    __half *pQa, *pKa, *pVa, *pQh, *pKh, *pVh, *pAOh, *pWqh, *pWkh, *pWvh, *pWoh;
    cudaGetSymbolAddress((void**)&pQa,  g_Qa);
    cudaGetSymbolAddress((void**)&pKa,  g_Ka);
    cudaGetSymbolAddress((void**)&pVa,  g_Va);
    cudaGetSymbolAddress((void**)&pQh,  g_Qh);
    cudaGetSymbolAddress((void**)&pKh,  g_Kh);
    cudaGetSymbolAddress((void**)&pVh,  g_Vh);
    cudaGetSymbolAddress((void**)&pAOh, g_AOh);
    cudaGetSymbolAddress((void**)&pWqh, g_Wqh);
    cudaGetSymbolAddress((void**)&pWkh, g_Wkh);
    cudaGetSymbolAddress((void**)&pWvh, g_Wvh);
    cudaGetSymbolAddress((void**)&pWoh, g_Woh);

    cudaFuncSetAttribute(gemm_f16n<0>, cudaFuncAttributeMaxDynamicSharedMemorySize, GN_SMEM);
    cudaFuncSetAttribute(gemm_f16n<1>, cudaFuncAttributeMaxDynamicSharedMemorySize, GN_SMEM);
    cudaFuncSetAttribute(gemm_f16n<2>, cudaFuncAttributeMaxDynamicSharedMemorySize, GN_SMEM);
    cudaFuncSetAttribute(flash4, cudaFuncAttributeMaxDynamicSharedMemorySize, FL4_SMEM);

    // one-shot conversion of everything to half
    ConvDesc cd;
    cd.src[0] = query; cd.dst[0] = pQa;  cd.nblk[0] = (MROWS * EMB) / 1024;
    cd.src[1] = key;   cd.dst[1] = pKa;  cd.nblk[1] = (MROWS * EMB) / 1024;
    cd.src[2] = value; cd.dst[2] = pVa;  cd.nblk[2] = (MROWS * EMB) / 1024;
    cd.src[3] = Wq;    cd.dst[3] = pWqh; cd.nblk[3] = (EMB * QDIM) / 1024;
    cd.src[4] = Wk;    cd.dst[4] = pWkh; cd.nblk[4] = (EMB * KVDIM) / 1024;
    cd.src[5] = Wv;    cd.dst[5] = pWvh; cd.nblk[5] = (EMB * KVDIM) / 1024;
    cd.src[6] = Wo;    cd.dst[6] = pWoh; cd.nblk[6] = (QDIM * EMB) / 1024;
    int total_blk = cd.nblk[0] + cd.nblk[1] + cd.nblk[2] + cd.nblk[3]
                  + cd.nblk[4] + cd.nblk[5] + cd.nblk[6];
    conv_all<<<total_blk, 256>>>(cd);

    // projections with fused epilogues
    gemm_f16n<2><<<dim3(QDIM  / 256, MROWS / 128), 256, GN_SMEM>>>(pQa, pWqh, pQh, MROWS, QDIM,  EMB, QSCALE);
    gemm_f16n<2><<<dim3(KVDIM / 256, MROWS / 128), 256, GN_SMEM>>>(pKa, pWkh, pKh, MROWS, KVDIM, EMB, 1.0f);
    gemm_f16n<1><<<dim3(KVDIM / 256, MROWS / 128), 256, GN_SMEM>>>(pVa, pWvh, pVh, MROWS, KVDIM, EMB, 0.f);

    // attention
    flash4<<<dim3(SEQ / 128, NH, BSZ), 256, FL4_SMEM>>>(pQh, pKh, pVh, pAOh);

    // output projection
    gemm_f16n<0><<<dim3(EMB / 256, MROWS / 128), 256, GN_SMEM>>>(pAOh, pWoh, out, MROWS, EMB, QDIM, 0.f);
}

// round 8
// speedup vs baseline: 1.1451x; 1.1451x over previous
#include <cuda_runtime.h>
#include <cuda_fp16.h>
#include <math.h>
#include <stdint.h>

#define BSZ   2
#define SEQ   2048
#define EMB   4096
#define NH    32
#define NKVH  8
#define HD    128
#define GROUPS (NH / NKVH)
#define MROWS (BSZ * SEQ)          // 4096
#define QDIM  (NH * HD)            // 4096
#define KVDIM (NKVH * HD)          // 1024

// log2(e)/sqrt(128), folded into Q so softmax uses bare exp2
#define QSCALE 0.12751744f

// Scratch (device globals)
__device__ __half g_Qa [(size_t)MROWS * EMB];    // half activations
__device__ __half g_Ka [(size_t)MROWS * EMB];
__device__ __half g_Va [(size_t)MROWS * EMB];
__device__ __half g_Qh [(size_t)MROWS * QDIM];   // post-rope half
__device__ __half g_Kh [(size_t)MROWS * KVDIM];
__device__ __half g_Vh [(size_t)MROWS * KVDIM];
__device__ __half g_AOh[(size_t)MROWS * QDIM];
__device__ __half g_Wqh[(size_t)EMB * QDIM];     // [K][N] half (no transpose)
__device__ __half g_Wkh[(size_t)EMB * KVDIM];
__device__ __half g_Wvh[(size_t)EMB * KVDIM];
__device__ __half g_Woh[(size_t)QDIM * EMB];

// ---------------------------------------------------------------------------
// Helpers
// ---------------------------------------------------------------------------
__device__ __forceinline__ uint32_t smem_u32(const void* p) {
    uint32_t a;
    asm("{ .reg .u64 t; cvta.to.shared.u64 t, %1; cvt.u32.u64 %0, t; }" : "=r"(a) : "l"(p));
    return a;
}
__device__ __forceinline__ void cpasync16(uint32_t dst, const void* src) {
    asm volatile("cp.async.cg.shared.global [%0], [%1], 16;" :: "r"(dst), "l"(src) : "memory");
}
#define CP_COMMIT() asm volatile("cp.async.commit_group;" ::: "memory")
#define CP_WAIT(n)  asm volatile("cp.async.wait_group %0;" :: "n"(n) : "memory")

__device__ __forceinline__ void mma_f16(float* d, const uint32_t* a, uint32_t b0, uint32_t b1) {
    asm volatile("mma.sync.aligned.m16n8k16.row.col.f32.f16.f16.f32 "
        "{%0,%1,%2,%3}, {%4,%5,%6,%7}, {%8,%9}, {%0,%1,%2,%3};"
        : "+f"(d[0]), "+f"(d[1]), "+f"(d[2]), "+f"(d[3])
        : "r"(a[0]), "r"(a[1]), "r"(a[2]), "r"(a[3]), "r"(b0), "r"(b1));
}
__device__ __forceinline__ void ldsm4(uint32_t& r0, uint32_t& r1, uint32_t& r2, uint32_t& r3,
                                      uint32_t addr) {
    asm volatile("ldmatrix.sync.aligned.m8n8.x4.shared.b16 {%0,%1,%2,%3}, [%4];"
        : "=r"(r0), "=r"(r1), "=r"(r2), "=r"(r3) : "r"(addr));
}
__device__ __forceinline__ void ldsm4t(uint32_t& r0, uint32_t& r1, uint32_t& r2, uint32_t& r3,
                                       uint32_t addr) {
    asm volatile("ldmatrix.sync.aligned.m8n8.x4.trans.shared.b16 {%0,%1,%2,%3}, [%4];"
        : "=r"(r0), "=r"(r1), "=r"(r2), "=r"(r3) : "r"(addr));
}

// ---------------------------------------------------------------------------
// One-shot fp32->half conversion of all 7 tensors. 1024 elems per block.
// ---------------------------------------------------------------------------
struct ConvDesc {
    const float* src[7];
    __half*      dst[7];
    int          nblk[7];
};

__global__ void conv_all(ConvDesc cd)
{
    int b = blockIdx.x;
    int seg = 0;
#pragma unroll
    for (int i = 0; i < 7; i++) {
        if (b >= cd.nblk[i]) { b -= cd.nblk[i]; seg = i + 1; }
        else break;
    }
    const float* src = cd.src[seg];
    __half* dst = cd.dst[seg];
    size_t i = ((size_t)b * 256 + threadIdx.x) * 4;
    float4 v = *(const float4*)(src + i);
    *(__half2*)(dst + i)     = __floats2half2_rn(v.x, v.y);
    *(__half2*)(dst + i + 2) = __floats2half2_rn(v.z, v.w);
}

// ---------------------------------------------------------------------------
// fp16 tensor-core GEMM: C[M,N] = A[M,K] @ B[K,N]  (B row-major, ldsm trans)
// CTA tile 128x128, BK=64, 8 warps (warp tile 64x32), cp.async 3-stage,
// 2 CTAs/SM, single barrier per k-iter.
// MODE: 0 = fp32 out, 1 = half out, 2 = rope(+scale) half out.
// ---------------------------------------------------------------------------
#define HP  72                    // A row pitch (halves)
#define BPN 136                   // B row pitch (halves)
#define SPN 132                   // fp32 staging pitch (floats), MODE 2
#define A_ST (128 * HP)           // halves
#define B_ST (64 * BPN)           // halves
#define STG_B ((A_ST + B_ST) * 2)            // 35840 bytes
#define GN_SMEM (3 * STG_B)                  // 107520 bytes

template <int MODE>
__global__ __launch_bounds__(256, 2) void gemm_f16n(const __half* __restrict__ A,
                                                    const __half* __restrict__ B,
                                                    void* __restrict__ Cv,
                                                    int M, int N, int K, float rsc)
{
    extern __shared__ __half smh[];
    const uint32_t sb = smem_u32(smh);

    const int tid  = threadIdx.x;
    const int wid  = tid >> 5, lane = tid & 31;
    const int g    = lane >> 2, tig = lane & 3;
    const int wm   = (wid >> 2) * 64;        // 0,64
    const int wn   = (wid & 3) * 32;         // 0..96
    const int bm   = blockIdx.y * 128, bn = blockIdx.x * 128;

    auto load_tile = [&](int c, int s) {
        const __half* Ab = A + (size_t)bm * K + c * 64;
        const __half* Bb = B + (size_t)(c * 64) * N + bn;
        uint32_t sa  = sb + (uint32_t)s * STG_B;
        uint32_t sbb = sa + A_ST * 2;
#pragma unroll
        for (int l = 0; l < 4; l++) {
            int id = l * 256 + tid;
            int ra = id >> 3, ca = (id & 7) * 8;         // A: 128 x 64
            cpasync16(sa + (uint32_t)(ra * HP + ca) * 2, Ab + (size_t)ra * K + ca);
            int rb = id >> 4, cb = (id & 15) * 8;        // B: 64 x 128
            cpasync16(sbb + (uint32_t)(rb * BPN + cb) * 2, Bb + (size_t)rb * N + cb);
        }
        CP_COMMIT();
    };

    const int l7  = lane & 7;
    const int lb3 = (lane >> 3) & 1;
    const int lb4 = lane >> 4;

    float acc[4][4][4];
#pragma unroll
    for (int mi = 0; mi < 4; mi++)
#pragma unroll
        for (int ni = 0; ni < 4; ni++)
#pragma unroll
            for (int r = 0; r < 4; r++) acc[mi][ni][r] = 0.0f;

    const int iters = K / 64;
    load_tile(0, 0);
    load_tile(1, 1);

    for (int c = 0; c < iters; c++) {
        const int s = c % 3;
        if (c + 1 < iters) { CP_WAIT(1); } else { CP_WAIT(0); }
        __syncthreads();
        if (c + 2 < iters) load_tile(c + 2, (c + 2) % 3);

        const uint32_t sA  = sb + (uint32_t)s * STG_B;
        const uint32_t sBb = sA + A_ST * 2;

#pragma unroll
        for (int ks = 0; ks < 4; ks++) {
            const int kb = ks * 16;
            uint32_t af[4][4], bf[2][4];
#pragma unroll
            for (int mi = 0; mi < 4; mi++) {
                uint32_t addr = sA + (uint32_t)((wm + mi * 16 + l7 + lb3 * 8) * HP
                                                + kb + lb4 * 8) * 2;
                ldsm4(af[mi][0], af[mi][1], af[mi][2], af[mi][3], addr);
            }
#pragma unroll
            for (int nj = 0; nj < 2; nj++) {
                uint32_t addr = sBb + (uint32_t)((kb + l7 + lb3 * 8) * BPN
                                                 + wn + nj * 16 + lb4 * 8) * 2;
                ldsm4t(bf[nj][0], bf[nj][1], bf[nj][2], bf[nj][3], addr);
            }
#pragma unroll
            for (int mi = 0; mi < 4; mi++)
#pragma unroll
                for (int nj = 0; nj < 2; nj++) {
                    mma_f16(acc[mi][nj * 2],     af[mi], bf[nj][0], bf[nj][1]);
                    mma_f16(acc[mi][nj * 2 + 1], af[mi], bf[nj][2], bf[nj][3]);
                }
        }
    }

    if (MODE == 2) {
        // stage fp32 tile in smem, apply RoPE (+scale), write half
        __syncthreads();
        float* S = (float*)smh;
#pragma unroll
        for (int mi = 0; mi < 4; mi++) {
            int r0 = wm + mi * 16 + g;
#pragma unroll
            for (int ni = 0; ni < 4; ni++) {
                int cc = wn + ni * 8 + tig * 2;
                *(float2*)(S + (size_t)r0 * SPN + cc)       = make_float2(acc[mi][ni][0], acc[mi][ni][1]);
                *(float2*)(S + (size_t)(r0 + 8) * SPN + cc) = make_float2(acc[mi][ni][2], acc[mi][ni][3]);
            }
        }
        __syncthreads();
        // tile is 128 wide = exactly one head (bn is head-aligned)
        __half* C = (__half*)Cv;
        const float LG = 0.2076205059304640f;   // 2*log2(10000)/128
#pragma unroll 4
        for (int l = 0; l < 32; l++) {
            int idx = l * 256 + tid;             // 8192 rotation pairs
            int r  = idx >> 6;
            int d  = idx & 63;
            float x1 = S[(size_t)r * SPN + d];
            float x2 = S[(size_t)r * SPN + d + 64];
            int grow = bm + r;
            float pos = (float)(grow & (SEQ - 1));
            float invf = exp2f(-LG * (float)d);
            float ang = pos * invf;
            float sn, cs;
            sincosf(ang, &sn, &cs);
            size_t o = (size_t)grow * N + bn + d;
            C[o]      = __float2half((x1 * cs - x2 * sn) * rsc);
            C[o + 64] = __float2half((x2 * cs + x1 * sn) * rsc);
        }
    } else {
#pragma unroll
        for (int mi = 0; mi < 4; mi++) {
            int row0 = bm + wm + mi * 16 + g;
#pragma unroll
            for (int ni = 0; ni < 4; ni++) {
                int col = bn + wn + ni * 8 + tig * 2;
                if (MODE == 1) {
                    __half* C = (__half*)Cv;
                    *(__half2*)(C + (size_t)row0 * N + col) =
                        __floats2half2_rn(acc[mi][ni][0], acc[mi][ni][1]);
                    *(__half2*)(C + (size_t)(row0 + 8) * N + col) =
                        __floats2half2_rn(acc[mi][ni][2], acc[mi][ni][3]);
                } else {
                    float* C = (float*)Cv;
                    *(float2*)(C + (size_t)row0 * N + col)       = make_float2(acc[mi][ni][0], acc[mi][ni][1]);
                    *(float2*)(C + (size_t)(row0 + 8) * N + col) = make_float2(acc[mi][ni][2], acc[mi][ni][3]);
                }
            }
        }
    }
}

// ---------------------------------------------------------------------------
// Flash attention v4 (unchanged): fp16 MMA, ldmatrix, 3-stage K/V pipeline,
// one barrier per kv-iteration. Q tile 128, K tile 64, 8 warps.
// ---------------------------------------------------------------------------
#define QP 136
#define VP 72
#define KVST (2 * 64 * QP)
#define FL4_SMEM ((128*QP + 3*KVST + 128*VP) * 2)   // 157696 bytes

__global__ __launch_bounds__(256, 1) void flash4(const __half* __restrict__ Q,
                                                 const __half* __restrict__ K,
                                                 const __half* __restrict__ V,
                                                 __half* __restrict__ O)
{
    extern __shared__ __half hs[];
    __half* Qs  = hs;
    __half* KV0 = Qs + 128 * QP;
    __half* Ps  = KV0 + 3 * KVST;

    const uint32_t sbQ  = smem_u32(Qs);
    const uint32_t sbKV = smem_u32(KV0);
    const uint32_t sbP  = smem_u32(Ps);
    __half2* P2 = (__half2*)Ps;

    const int qi  = (int)gridDim.x - 1 - (int)blockIdx.x;
    const int h   = blockIdx.y;
    const int b   = blockIdx.z;
    const int kvh = h / GROUPS;
    const int tid = threadIdx.x;
    const int wid = tid >> 5, lane = tid & 31;
    const int g   = lane >> 2, tig = lane & 3;
    const int wq  = wid * 16;
    const int l7  = lane & 7;
    const int lb3 = (lane >> 3) & 1;
    const int lb4 = lane >> 4;

    const __half* Qg = Q + (size_t)(b * SEQ + qi * 128) * QDIM + h * HD;
    const __half* Kg = K + (size_t)(b * SEQ) * KVDIM + kvh * HD;
    const __half* Vg = V + (size_t)(b * SEQ) * KVDIM + kvh * HD;

    auto load_kv = [&](int kb, int s) {
        const __half* Kt = Kg + (size_t)(kb * 64) * KVDIM;
        const __half* Vt = Vg + (size_t)(kb * 64) * KVDIM;
        uint32_t ks_ = sbKV + (uint32_t)s * (KVST * 2);
        uint32_t vs_ = ks_ + 64 * QP * 2;
#pragma unroll
        for (int l = 0; l < 4; l++) {
            int id = l * 256 + tid;
            int r = id >> 4, c8 = (id & 15) * 8;
            cpasync16(ks_ + (uint32_t)(r * QP + c8) * 2, Kt + (size_t)r * KVDIM + c8);
            cpasync16(vs_ + (uint32_t)(r * QP + c8) * 2, Vt + (size_t)r * KVDIM + c8);
        }
        CP_COMMIT();
    };

#pragma unroll
    for (int l = 0; l < 8; l++) {
        int id = l * 256 + tid;
        int r = id >> 4, c8 = (id & 15) * 8;
        *(uint4*)(Qs + r * QP + c8) = *(const uint4*)(Qg + (size_t)r * QDIM + c8);
    }

    float m0 = -INFINITY, m1 = -INFINITY, l0 = 0.f, l1 = 0.f;
    float oa[16][4];
#pragma unroll
    for (int ni = 0; ni < 16; ni++)
#pragma unroll
        for (int r = 0; r < 4; r++) oa[ni][r] = 0.f;

    const int kmax = 2 * qi + 2;
    load_kv(0, 0);
    load_kv(1, 1);

    for (int kb = 0; kb < kmax; kb++) {
        const int s = kb % 3;
        if (kb + 1 < kmax) { CP_WAIT(1); } else { CP_WAIT(0); }
        __syncthreads();
        if (kb + 2 < kmax) load_kv(kb + 2, (kb + 2) % 3);

        const uint32_t sK = sbKV + (uint32_t)s * (KVST * 2);
        const uint32_t sV = sK + 64 * QP * 2;

        float sa[8][4];
#pragma unroll
        for (int ni = 0; ni < 8; ni++)
#pragma unroll
            for (int r = 0; r < 4; r++) sa[ni][r] = 0.f;

#pragma unroll
        for (int ks = 0; ks < 8; ks++) {
            const int kc = ks * 16;
            uint32_t a[4], bf[8][2];
            {
                uint32_t addr = sbQ + (uint32_t)((wq + l7 + lb3 * 8) * QP + kc + lb4 * 8) * 2;
                ldsm4(a[0], a[1], a[2], a[3], addr);
            }
#pragma unroll
            for (int nip = 0; nip < 4; nip++) {
                uint32_t addr = sK + (uint32_t)((nip * 16 + l7 + lb4 * 8) * QP + kc + lb3 * 8) * 2;
                ldsm4(bf[nip*2][0], bf[nip*2][1], bf[nip*2+1][0], bf[nip*2+1][1], addr);
            }
#pragma unroll
            for (int ni = 0; ni < 8; ni++)
                mma_f16(sa[ni], a, bf[ni][0], bf[ni][1]);
        }

        if (kb >= 2 * qi) {
            int r0 = qi * 128 + wq + g;
#pragma unroll
            for (int ni = 0; ni < 8; ni++) {
                int c0 = kb * 64 + ni * 8 + 2 * tig;
                if (c0 > r0)         sa[ni][0] = -INFINITY;
                if (c0 + 1 > r0)     sa[ni][1] = -INFINITY;
                if (c0 > r0 + 8)     sa[ni][2] = -INFINITY;
                if (c0 + 1 > r0 + 8) sa[ni][3] = -INFINITY;
            }
        }

        float mx0 = -INFINITY, mx1 = -INFINITY;
#pragma unroll
        for (int ni = 0; ni < 8; ni++) {
            mx0 = fmaxf(mx0, fmaxf(sa[ni][0], sa[ni][1]));
            mx1 = fmaxf(mx1, fmaxf(sa[ni][2], sa[ni][3]));
        }
        mx0 = fmaxf(mx0, __shfl_xor_sync(0xffffffffu, mx0, 1));
        mx0 = fmaxf(mx0, __shfl_xor_sync(0xffffffffu, mx0, 2));
        mx1 = fmaxf(mx1, __shfl_xor_sync(0xffffffffu, mx1, 1));
        mx1 = fmaxf(mx1, __shfl_xor_sync(0xffffffffu, mx1, 2));

        float mm0 = fmaxf(m0, mx0), mm1 = fmaxf(m1, mx1);
        float sub0 = (mm0 == -INFINITY) ? 0.f : mm0;
        float sub1 = (mm1 == -INFINITY) ? 0.f : mm1;
        float al0 = exp2f(m0 - sub0);
        float al1 = exp2f(m1 - sub1);
        m0 = mm0; m1 = mm1;

        float ls0 = 0.f, ls1 = 0.f;
#pragma unroll
        for (int ni = 0; ni < 8; ni++) {
            float p0 = exp2f(sa[ni][0] - sub0);
            float p1 = exp2f(sa[ni][1] - sub0);
            float p2 = exp2f(sa[ni][2] - sub1);
            float p3 = exp2f(sa[ni][3] - sub1);
            ls0 += p0 + p1; ls1 += p2 + p3;
            P2[(wq + g) * (VP/2) + ni * 4 + tig]     = __floats2half2_rn(p0, p1);
            P2[(wq + g + 8) * (VP/2) + ni * 4 + tig] = __floats2half2_rn(p2, p3);
        }
        ls0 += __shfl_xor_sync(0xffffffffu, ls0, 1);
        ls0 += __shfl_xor_sync(0xffffffffu, ls0, 2);
        ls1 += __shfl_xor_sync(0xffffffffu, ls1, 1);
        ls1 += __shfl_xor_sync(0xffffffffu, ls1, 2);
        l0 = l0 * al0 + ls0;
        l1 = l1 * al1 + ls1;

#pragma unroll
        for (int ni = 0; ni < 16; ni++) {
            oa[ni][0] *= al0; oa[ni][1] *= al0;
            oa[ni][2] *= al1; oa[ni][3] *= al1;
        }
        __syncwarp();

#pragma unroll
        for (int ks = 0; ks < 4; ks++) {
            const int kc = ks * 16;
            uint32_t a[4];
            {
                uint32_t addr = sbP + (uint32_t)((wq + l7 + lb3 * 8) * VP + kc + lb4 * 8) * 2;
                ldsm4(a[0], a[1], a[2], a[3], addr);
            }
#pragma unroll
            for (int nip = 0; nip < 8; nip++) {
                uint32_t bf0, bf1, bf2, bf3;
                uint32_t addr = sV + (uint32_t)((kc + l7 + lb3 * 8) * QP + nip * 16 + lb4 * 8) * 2;
                ldsm4t(bf0, bf1, bf2, bf3, addr);
                mma_f16(oa[nip*2],     a, bf0, bf1);
                mma_f16(oa[nip*2 + 1], a, bf2, bf3);
            }
        }
    }

    float inv0 = 1.0f / l0, inv1 = 1.0f / l1;
    __half* Og = O + (size_t)(b * SEQ + qi * 128 + wq) * QDIM + h * HD;
#pragma unroll
    for (int ni = 0; ni < 16; ni++) {
        int col = ni * 8 + 2 * tig;
        *(__half2*)(Og + (size_t)g * QDIM + col) =
            __floats2half2_rn(oa[ni][0] * inv0, oa[ni][1] * inv0);
        *(__half2*)(Og + (size_t)(g + 8) * QDIM + col) =
            __floats2half2_rn(oa[ni][2] * inv1, oa[ni][3] * inv1);
    }
}

// ---------------------------------------------------------------------------
// Launch: conv_all -> gemmQ(rope) -> gemmK(rope) -> gemmV(half) -> flash -> gemmO
// ---------------------------------------------------------------------------
extern "C" void kernel_launch(void* const* d_in, const int* in_sizes, int n_in,
                              void* d_out, int out_size)
{
    const float* query = (const float*)d_in[0];
    const float* key   = (const float*)d_in[1];
    const float* value = (const float*)d_in[2];
    const float* Wq = (const float*)d_in[5];
    const float* Wk = (const float*)d_in[6];
    const float* Wv = (const float*)d_in[7];
    const float* Wo = (const float*)d_in[8];
    float* out = (float*)d_out;

    __half *pQa, *pKa, *pVa, *pQh, *pKh, *pVh, *pAOh, *pWqh, *pWkh, *pWvh, *pWoh;
    cudaGetSymbolAddress((void**)&pQa,  g_Qa);
    cudaGetSymbolAddress((void**)&pKa,  g_Ka);
    cudaGetSymbolAddress((void**)&pVa,  g_Va);
    cudaGetSymbolAddress((void**)&pQh,  g_Qh);
    cudaGetSymbolAddress((void**)&pKh,  g_Kh);
    cudaGetSymbolAddress((void**)&pVh,  g_Vh);
    cudaGetSymbolAddress((void**)&pAOh, g_AOh);
    cudaGetSymbolAddress((void**)&pWqh, g_Wqh);
    cudaGetSymbolAddress((void**)&pWkh, g_Wkh);
    cudaGetSymbolAddress((void**)&pWvh, g_Wvh);
    cudaGetSymbolAddress((void**)&pWoh, g_Woh);

    cudaFuncSetAttribute(gemm_f16n<0>, cudaFuncAttributeMaxDynamicSharedMemorySize, GN_SMEM);
    cudaFuncSetAttribute(gemm_f16n<1>, cudaFuncAttributeMaxDynamicSharedMemorySize, GN_SMEM);
    cudaFuncSetAttribute(gemm_f16n<2>, cudaFuncAttributeMaxDynamicSharedMemorySize, GN_SMEM);
    cudaFuncSetAttribute(flash4, cudaFuncAttributeMaxDynamicSharedMemorySize, FL4_SMEM);

    // one-shot conversion of everything to half
    ConvDesc cd;
    cd.src[0] = query; cd.dst[0] = pQa;  cd.nblk[0] = (MROWS * EMB) / 1024;
    cd.src[1] = key;   cd.dst[1] = pKa;  cd.nblk[1] = (MROWS * EMB) / 1024;
    cd.src[2] = value; cd.dst[2] = pVa;  cd.nblk[2] = (MROWS * EMB) / 1024;
    cd.src[3] = Wq;    cd.dst[3] = pWqh; cd.nblk[3] = (EMB * QDIM) / 1024;
    cd.src[4] = Wk;    cd.dst[4] = pWkh; cd.nblk[4] = (EMB * KVDIM) / 1024;
    cd.src[5] = Wv;    cd.dst[5] = pWvh; cd.nblk[5] = (EMB * KVDIM) / 1024;
    cd.src[6] = Wo;    cd.dst[6] = pWoh; cd.nblk[6] = (QDIM * EMB) / 1024;
    int total_blk = cd.nblk[0] + cd.nblk[1] + cd.nblk[2] + cd.nblk[3]
                  + cd.nblk[4] + cd.nblk[5] + cd.nblk[6];
    conv_all<<<total_blk, 256>>>(cd);

    // projections with fused epilogues
    gemm_f16n<2><<<dim3(QDIM  / 128, MROWS / 128), 256, GN_SMEM>>>(pQa, pWqh, pQh, MROWS, QDIM,  EMB, QSCALE);
    gemm_f16n<2><<<dim3(KVDIM / 128, MROWS / 128), 256, GN_SMEM>>>(pKa, pWkh, pKh, MROWS, KVDIM, EMB, 1.0f);
    gemm_f16n<1><<<dim3(KVDIM / 128, MROWS / 128), 256, GN_SMEM>>>(pVa, pWvh, pVh, MROWS, KVDIM, EMB, 0.f);

    // attention
    flash4<<<dim3(SEQ / 128, NH, BSZ), 256, FL4_SMEM>>>(pQh, pKh, pVh, pAOh);

    // output projection
    gemm_f16n<0><<<dim3(EMB / 128, MROWS / 128), 256, GN_SMEM>>>(pAOh, pWoh, out, MROWS, EMB, QDIM, 0.f);
}